// round 3
// baseline (speedup 1.0000x reference)
#include <cuda_runtime.h>
#include <math.h>

// Shapes (fixed by dataset):
//   features: [B=2, C=512, H=50, W=64] float32
//   roiss   : [B=2, N=128, 4]          float32
//   out     : [B, N, C]                float32
#define BB 2
#define CC 512
#define HH 50
#define WW 64
#define NN 128
#define HWSZ (HH * WW)   // 3200

// Scratch: features transposed to [B, H, W, C]  (13.1 MB)
__device__ float g_tfeat[BB * HWSZ * CC];

// ---------------------------------------------------------------------------
// Kernel 1: transpose [B, C, HW] -> [B, HW, C] with 32x32 smem tiles.
// ---------------------------------------------------------------------------
__global__ __launch_bounds__(256) void transpose_kernel(
    const float* __restrict__ feat)
{
    __shared__ float tile[32][33];

    const int b   = blockIdx.z;
    const int c0  = blockIdx.y * 32;   // C tile origin
    const int hw0 = blockIdx.x * 32;   // HW tile origin
    const int tx  = threadIdx.x;       // 0..31
    const int ty  = threadIdx.y;       // 0..7

    const float* src = feat + (size_t)b * CC * HWSZ;
    float* dst       = g_tfeat + (size_t)b * HWSZ * CC;

    #pragma unroll
    for (int j = 0; j < 32; j += 8)
        tile[ty + j][tx] = src[(size_t)(c0 + ty + j) * HWSZ + (hw0 + tx)];
    __syncthreads();

    #pragma unroll
    for (int j = 0; j < 32; j += 8)
        dst[(size_t)(hw0 + ty + j) * CC + (c0 + tx)] = tile[tx][ty + j];
}

// ---------------------------------------------------------------------------
// Kernel 2: ROI max-pool from [B, H, W, C].
//   grid  = (B*N, 2)   — blockIdx.x = roi, blockIdx.y = channel half
//   block = 256        — 64 float4 channel-lanes x 4 row-groups
// Row-group g handles window rows y1+g, y1+g+4, ...; partials combine in smem.
// All window loads in a thread are independent -> one latency wave.
// ---------------------------------------------------------------------------
__global__ __launch_bounds__(256) void pool_kernel(
    const float* __restrict__ rois,
    float* __restrict__ out)
{
    const int bn = blockIdx.x;               // 0 .. B*N-1
    const int b  = bn / NN;
    const int c4 = threadIdx.x & 63;         // float4 channel lane (0..63)
    const int g  = threadIdx.x >> 6;         // row group (0..3)
    const int c  = blockIdx.y * 256 + c4 * 4; // first channel of this lane

    // --- box computation (byte-identical to jax reference path) ---
    const float4 r = reinterpret_cast<const float4*>(rois)[bn];
    const float nx1 = __fmul_rn(__fdiv_rn(r.x, 1024.0f), (float)WW);
    const float ny1 = __fmul_rn(__fdiv_rn(r.y,  800.0f), (float)HH);
    const float nx2 = __fmul_rn(__fdiv_rn(r.z, 1024.0f), (float)WW);
    const float ny2 = __fmul_rn(__fdiv_rn(r.w,  800.0f), (float)HH);

    int x1 = max((int)floorf(nx1), 0);
    int y1 = max((int)floorf(ny1), 0);
    int x2 = max((int)ceilf(nx2), 0);
    int y2 = max((int)ceilf(ny2), 0);

    if (x1 == 0 && x2 == 0) x2 = 1;
    if (y1 == 0 && y2 == 0) y2 = 1;
    if (x1 >= WW) x1 = WW - 1;
    if (y1 >= HH) y1 = HH - 1;

    const int xe = min(x2, WW);
    const int ye = min(y2, HH);

    const float* base = g_tfeat + (size_t)b * HWSZ * CC + c;

    float4 m = make_float4(-INFINITY, -INFINITY, -INFINITY, -INFINITY);

    // Rows y1+g, y1+g+4, ... (window height <= 7 here -> <= 2 iterations)
    for (int y = y1 + g; y < ye; y += 4) {
        const float* row = base + (size_t)(y * WW) * CC;
        // window width <= 7 for this dataset; 8 predicated LDG.128 -> MLP=8
        #pragma unroll
        for (int i = 0; i < 8; ++i) {
            const int x = x1 + i;
            if (x < xe) {
                const float4 v =
                    *reinterpret_cast<const float4*>(row + (size_t)x * CC);
                m.x = fmaxf(m.x, v.x);
                m.y = fmaxf(m.y, v.y);
                m.z = fmaxf(m.z, v.z);
                m.w = fmaxf(m.w, v.w);
            }
        }
        for (int x = x1 + 8; x < xe; ++x) {  // safety, never taken here
            const float4 v =
                *reinterpret_cast<const float4*>(row + (size_t)x * CC);
            m.x = fmaxf(m.x, v.x);
            m.y = fmaxf(m.y, v.y);
            m.z = fmaxf(m.z, v.z);
            m.w = fmaxf(m.w, v.w);
        }
    }

    __shared__ float4 part[4][64];
    part[g][c4] = m;
    __syncthreads();

    if (g == 0) {
        float4 a = part[0][c4];
        const float4 b1 = part[1][c4];
        const float4 b2 = part[2][c4];
        const float4 b3 = part[3][c4];
        a.x = fmaxf(fmaxf(a.x, b1.x), fmaxf(b2.x, b3.x));
        a.y = fmaxf(fmaxf(a.y, b1.y), fmaxf(b2.y, b3.y));
        a.z = fmaxf(fmaxf(a.z, b1.z), fmaxf(b2.z, b3.z));
        a.w = fmaxf(fmaxf(a.w, b1.w), fmaxf(b2.w, b3.w));
        *reinterpret_cast<float4*>(out + (size_t)bn * CC + c) = a;
    }
}

extern "C" void kernel_launch(void* const* d_in, const int* in_sizes, int n_in,
                              void* d_out, int out_size)
{
    const float* feat = (const float*)d_in[0];   // [B, C, H, W]
    const float* rois = (const float*)d_in[1];   // [B, N, 4]
    float* out        = (float*)d_out;           // [B, N, C]
    (void)in_sizes; (void)n_in; (void)out_size;

    dim3 tgrid(HWSZ / 32, CC / 32, BB);          // 100 x 16 x 2
    dim3 tblock(32, 8);
    transpose_kernel<<<tgrid, tblock>>>(feat);

    dim3 pgrid(BB * NN, 2);                      // 256 x 2
    pool_kernel<<<pgrid, 256>>>(rois, out);
}